// round 6
// baseline (speedup 1.0000x reference)
#include <cuda_runtime.h>
#include <math_constants.h>

#define BB 64
#define SS 512
#define TT 128
#define NT 256
#define GB 2              // batches per block
#define NBLK (BB / GB)    // 32

__device__ float g_partial[BB];
__device__ unsigned int g_ctr = 0;

static __device__ __forceinline__ unsigned long long ffma2(unsigned long long a,
                                                           unsigned long long b,
                                                           unsigned long long c) {
    unsigned long long d;
    asm("fma.rn.f32x2 %0, %1, %2, %3;" : "=l"(d) : "l"(a), "l"(b), "l"(c));
    return d;
}
static __device__ __forceinline__ unsigned long long addf2(unsigned long long a,
                                                           unsigned long long b) {
    unsigned long long d;
    asm("add.rn.f32x2 %0, %1, %2;" : "=l"(d) : "l"(a), "l"(b));
    return d;
}
static __device__ __forceinline__ unsigned long long pack2(float x, float y) {
    unsigned long long d;
    asm("mov.b64 %0, {%1, %2};" : "=l"(d) : "f"(x), "f"(y));
    return d;
}
static __device__ __forceinline__ float2 unpack2(unsigned long long v) {
    float2 r;
    asm("mov.b64 {%0, %1}, %2;" : "=f"(r.x), "=f"(r.y) : "l"(v));
    return r;
}

__global__ __launch_bounds__(NT, 1)
void crf_kernel(const float* __restrict__ feats,
                const int* __restrict__ mask,
                const int* __restrict__ tags,
                const float* __restrict__ trans,
                const float* __restrict__ start_t,
                const float* __restrict__ stop_t,
                float* __restrict__ out)
{
    __shared__ __align__(16) float sh_qA[2][TT];  // batch A partition, double-buffered
    __shared__ __align__(16) float sh_qB[2][TT];  // batch B partition
    __shared__ int sh_mk[GB][SS];
    __shared__ float sh_v[TT];
    __shared__ float sh_wmax[4];
    __shared__ float sh_redf[NT / 32];
    __shared__ float sh_redl[NT / 32];
    __shared__ int sh_last;

    const int b0 = blockIdx.x * GB;
    const int t = threadIdx.x;
    const float* FbA = feats + (size_t)b0 * SS * TT;
    const float* FbB = feats + (size_t)(b0 + 1) * SS * TT;

    const int w = t >> 5;
    const int l = t & 31;
    const int j = w * 16 + (l >> 1);  // output column
    const int half = l & 1;
    const int i0 = half * 64;

    // preload masks
    for (int s = t; s < SS; s += NT) {
        sh_mk[0][s] = mask[b0 * SS + s];
        sh_mk[1][s] = mask[(b0 + 1) * SS + s];
    }

    // E[i][j] = exp(trans[j][i]) — shared by both batches
    unsigned long long e2[32];
#pragma unroll
    for (int k = 0; k < 32; k++) {
        float2 tv = *(const float2*)(trans + j * TT + i0 + 2 * k);
        e2[k] = pack2(__expf(tv.x), __expf(tv.y));
    }

    // ---- init both batches ----
    float qjA = __expf(FbA[j] + start_t[j]);
    float qjB = __expf(FbB[j] + start_t[j]);
    if (half == 0) { sh_qA[0][j] = qjA; sh_qB[0][j] = qjB; }
    int CexpA = 0, CexpB = 0;
    float efA = __expf(FbA[1 * TT + j]);
    float efB = __expf(FbB[1 * TT + j]);
    float fnxA = FbA[2 * TT + j], fnxB = FbB[2 * TT + j];
    float fnx2A = FbA[3 * TT + j], fnx2B = FbB[3 * TT + j];
    __syncthreads();

    // ---- sequential scan: two independent chains per thread, one barrier ----
#pragma unroll 2
    for (int s = 1; s < SS; s++) {
        const int p = (s - 1) & 1;

        // phase A (both batches): exact pow2 normalizers, prefetches
        float q0A = sh_qA[p][0], q0B = sh_qB[p][0];
        int eA = (__float_as_int(q0A) >> 23) - 127;
        int eB = (__float_as_int(q0B) >> 23) - 127;
        float rinvA = __int_as_float((127 - eA) << 23);
        float rinvB = __int_as_float((127 - eB) << 23);
        CexpA += eA; CexpB += eB;
        float scA = efA * rinvA, scB = efB * rinvB;
        float efnA = __expf(fnxA), efnB = __expf(fnxB);
        int sp3 = (s + 3 < SS) ? (s + 3) : (SS - 1);
        float fnewA = FbA[(size_t)sp3 * TT + j];
        float fnewB = FbB[(size_t)sp3 * TT + j];
        int mA = sh_mk[0][s], mB = sh_mk[1][s];

        // phase B: interleaved matvec partials (i in [i0,i0+64), column j)
        const ulonglong2* qA8 = (const ulonglong2*)(&sh_qA[p][i0]);
        const ulonglong2* qB8 = (const ulonglong2*)(&sh_qB[p][i0]);
        unsigned long long a0A = 0ull, a1A = 0ull, a2A = 0ull, a3A = 0ull;
        unsigned long long a0B = 0ull, a1B = 0ull, a2B = 0ull, a3B = 0ull;
#pragma unroll
        for (int k = 0; k < 16; k += 2) {
            ulonglong2 vA0 = qA8[k], vA1 = qA8[k + 1];
            ulonglong2 vB0 = qB8[k], vB1 = qB8[k + 1];
            a0A = ffma2(e2[2 * k + 0], vA0.x, a0A);
            a0B = ffma2(e2[2 * k + 0], vB0.x, a0B);
            a1A = ffma2(e2[2 * k + 1], vA0.y, a1A);
            a1B = ffma2(e2[2 * k + 1], vB0.y, a1B);
            a2A = ffma2(e2[2 * k + 2], vA1.x, a2A);
            a2B = ffma2(e2[2 * k + 2], vB1.x, a2B);
            a3A = ffma2(e2[2 * k + 3], vA1.y, a3A);
            a3B = ffma2(e2[2 * k + 3], vB1.y, a3B);
        }
        unsigned long long spA = addf2(addf2(a0A, a1A), addf2(a2A, a3A));
        unsigned long long spB = addf2(addf2(a0B, a1B), addf2(a2B, a3B));
        float2 aA = unpack2(spA), aB = unpack2(spB);
        float partA = aA.x + aA.y, partB = aB.x + aB.y;

        float ssumA = partA + __shfl_xor_sync(0xffffffffu, partA, 1);
        float ssumB = partB + __shfl_xor_sync(0xffffffffu, partB, 1);

        qjA = mA ? (ssumA * scA) : (qjA * rinvA);
        qjB = mB ? (ssumB * scB) : (qjB * rinvB);
        if (half == 0) { sh_qA[s & 1][j] = qjA; sh_qB[s & 1][j] = qjB; }

        efA = efnA; fnxA = fnx2A; fnx2A = fnewA;
        efB = efnB; fnxB = fnx2B; fnx2B = fnewB;
        __syncthreads();
    }

    // ---- per-batch epilogue: fwd LSE + gold score (cheap, sequential over GB) ----
    for (int g = 0; g < GB; g++) {
        const float* Fb = (g == 0) ? FbA : FbB;
        const int* Tg = tags + (b0 + g) * SS;
        float qj = (g == 0) ? qjA : qjB;
        int Cexp = (g == 0) ? CexpA : CexpB;

        if (half == 0) sh_v[j] = (float)Cexp * 0.69314718055994531f + __logf(qj) + stop_t[j];
        __syncthreads();

        float v = -CUDART_INF_F;
        if (t < TT) {
            v = sh_v[t];
            float m = v;
#pragma unroll
            for (int o = 16; o; o >>= 1) m = fmaxf(m, __shfl_xor_sync(0xffffffffu, m, o));
            if ((t & 31) == 0) sh_wmax[t >> 5] = m;
        }
        __syncthreads();
        float M = fmaxf(fmaxf(sh_wmax[0], sh_wmax[1]), fmaxf(sh_wmax[2], sh_wmax[3]));
        if (t < TT) {
            float e = __expf(v - M);
#pragma unroll
            for (int o = 16; o; o >>= 1) e += __shfl_xor_sync(0xffffffffu, e, o);
            if ((t & 31) == 0) sh_redf[t >> 5] = e;
        }
        __syncthreads();
        float fwd = 0.f;
        if (t == 0) {
            float es = sh_redf[0] + sh_redf[1] + sh_redf[2] + sh_redf[3];
            fwd = M + __logf(es);
        }
        __syncthreads();

        float facc = 0.f, lacc = 0.f;
        for (int s = t; s < SS; s += NT) {
            float mk = (float)sh_mk[g][s];
            int tg = Tg[s];
            facc += Fb[(size_t)s * TT + tg] * mk;
            lacc += mk;
            if (s >= 1) facc += trans[Tg[s - 1] * TT + tg] * mk;
        }
#pragma unroll
        for (int o = 16; o; o >>= 1) {
            facc += __shfl_xor_sync(0xffffffffu, facc, o);
            lacc += __shfl_xor_sync(0xffffffffu, lacc, o);
        }
        if ((t & 31) == 0) {
            sh_redf[t >> 5] = facc;
            sh_redl[t >> 5] = lacc;
        }
        __syncthreads();
        if (t == 0) {
            float fs = 0.f, ls = 0.f;
#pragma unroll
            for (int x = 0; x < NT / 32; x++) { fs += sh_redf[x]; ls += sh_redl[x]; }
            int len = (int)(ls + 0.5f);
            float gold = fs + start_t[Tg[0]] + stop_t[Tg[len - 1]];
            g_partial[b0 + g] = fwd - gold;
        }
        __syncthreads();
    }

    // ---- fused deterministic final reduction ----
    if (t == 0) {
        __threadfence();
        unsigned int old = atomicInc(&g_ctr, NBLK - 1);  // wraps to 0 each launch
        sh_last = (old == NBLK - 1) ? 1 : 0;
    }
    __syncthreads();
    if (sh_last) {
        if (t < BB) {
            float acc = __ldcg(&g_partial[t]);
#pragma unroll
            for (int o = 16; o; o >>= 1) acc += __shfl_xor_sync(0xffffffffu, acc, o);
            if ((t & 31) == 0) sh_redf[t >> 5] = acc;
        }
        __syncthreads();
        if (t == 0) out[0] = sh_redf[0] + sh_redf[1];
    }
}

extern "C" void kernel_launch(void* const* d_in, const int* in_sizes, int n_in,
                              void* d_out, int out_size) {
    const float* feats = (const float*)d_in[0];
    const int* mask = (const int*)d_in[1];
    const int* tags = (const int*)d_in[2];
    const float* trans = (const float*)d_in[3];
    const float* start_t = (const float*)d_in[4];
    const float* stop_t = (const float*)d_in[5];
    float* out = (float*)d_out;

    crf_kernel<<<NBLK, NT>>>(feats, mask, tags, trans, start_t, stop_t, out);
}